// round 15
// baseline (speedup 1.0000x reference)
#include <cuda_runtime.h>
#include <cuda_bf16.h>
#include <stdint.h>

#define B 128
#define C 1024
#define MARGIN 1.0f
#define THREADS 256
#define NWARP (THREADS / 32)
#define MAX_POS 256
#define VEC 4                 // C / THREADS

// Per-row (loss, denom) partials — distinct addresses, no contention.
__device__ float2 g_part[B];
// Last-block-done ticket; reset by the finishing block -> replay-safe.
__device__ unsigned int g_ticket;

// acq_rel RMW: release orders this block's prior partial store; for the block
// that observes ticket==B-1 it is also the acquire for reading all partials.
__device__ __forceinline__ unsigned int ticket_acq_rel_inc() {
    unsigned int t;
    asm volatile("atom.acq_rel.gpu.global.add.u32 %0, [%1], %2;"
                 : "=r"(t) : "l"(&g_ticket), "r"(1u) : "memory");
    return t;
}

__global__ void __launch_bounds__(THREADS, 1)
fused_kernel(const float* __restrict__ scores, const uint4* __restrict__ pos_mask,
             float* __restrict__ out) {
    const int row  = blockIdx.x;
    const int tid  = threadIdx.x;
    const int w    = tid >> 5;
    const int lane = tid & 31;

    __shared__ float s_pos[MAX_POS];
    __shared__ int   s_npos;
    __shared__ float s_red[NWARP];

    if (tid == 0) s_npos = 0;

    // Mask is a 32-bit dtype (float32 or int32 — established empirically).
    // For both: positive <=> 32-bit word != 0.
    // Scores + mask loads are independent: back-to-back, one latency round.
    const float4 sc4 = ((const float4*)(scores + row * C))[tid];
    const uint4  mv  = pos_mask[row * (C / VEC) + tid];

    __syncthreads();   // s_npos init visible; overlaps the in-flight loads

    float sc[VEC] = {sc4.x, sc4.y, sc4.z, sc4.w};
    bool  m[VEC]  = {mv.x != 0u, mv.y != 0u, mv.z != 0u, mv.w != 0u};

    // ---- Gather positive scores into SMEM (few positives -> cheap) ----
#pragma unroll
    for (int k = 0; k < VEC; k++) {
        if (m[k]) {
            int slot = atomicAdd(&s_npos, 1);
            if (slot < MAX_POS) s_pos[slot] = sc[k];
        }
    }
    __syncthreads();

    const int npos = min(s_npos, MAX_POS);

    // ---- Pairwise hinge with 4 independent accumulators (dep chain = npos) ----
    float a0 = 0.0f, a1 = 0.0f, a2 = 0.0f, a3 = 0.0f;
    {
        const float n0 = sc[0] + MARGIN, n1 = sc[1] + MARGIN;
        const float n2 = sc[2] + MARGIN, n3 = sc[3] + MARGIN;
        for (int p = 0; p < npos; p++) {
            const float sp = s_pos[p];
            if (!m[0]) a0 += fmaxf(n0 - sp, 0.0f);
            if (!m[1]) a1 += fmaxf(n1 - sp, 0.0f);
            if (!m[2]) a2 += fmaxf(n2 - sp, 0.0f);
            if (!m[3]) a3 += fmaxf(n3 - sp, 0.0f);
        }
    }
    float acc = (a0 + a1) + (a2 + a3);

    // ---- Deterministic block reduction ----
#pragma unroll
    for (int off = 16; off > 0; off >>= 1)
        acc += __shfl_down_sync(0xFFFFFFFFu, acc, off);
    if (lane == 0) s_red[w] = acc;
    __syncthreads();

    // ---- Warp 0 only: publish partial, grab ticket, maybe finalize.
    //      Warps 1..7 exit here (faster CTA drain). ----
    if (w == 0) {
        unsigned int ticket = 0;
        if (lane == 0) {
            // pairwise tree over 8 warp sums (fixed order -> deterministic)
            float t0 = s_red[0] + s_red[1];
            float t1 = s_red[2] + s_red[3];
            float t2 = s_red[4] + s_red[5];
            float t3 = s_red[6] + s_red[7];
            float total = (t0 + t1) + (t2 + t3);
            float np = (float)npos;
            __stcg(&g_part[row], make_float2(total, np * (float)(C - npos)));
            ticket = ticket_acq_rel_inc();  // release partial, fetch ticket
        }
        ticket = __shfl_sync(0xFFFFFFFFu, ticket, 0);

        if (ticket == B - 1) {
            // Last block: acquire done by the acq_rel atomic. Fixed-order,
            // bitwise-deterministic reduction of 128 partials in one warp.
            // 128 float2 = 64 float4: 2 vector loads per lane.
            const float4* p4 = (const float4*)g_part;
            float4 q0 = __ldcg(&p4[lane]);
            float4 q1 = __ldcg(&p4[lane + 32]);
            float l = q0.x + q0.z + q1.x + q1.z;
            float d = q0.y + q0.w + q1.y + q1.w;
#pragma unroll
            for (int off = 16; off > 0; off >>= 1) {
                l += __shfl_down_sync(0xFFFFFFFFu, l, off);
                d += __shfl_down_sync(0xFFFFFFFFu, d, off);
            }
            if (lane == 0) {
                out[0] = (d == 0.0f) ? 0.0f : l / d;
                g_ticket = 0;  // reset for next graph replay
            }
        }
    }
}

extern "C" void kernel_launch(void* const* d_in, const int* in_sizes, int n_in,
                              void* d_out, int out_size) {
    const float* scores = (const float*)d_in[0];
    const uint4* pos_mask = (const uint4*)d_in[1];
    float* out = (float*)d_out;

    fused_kernel<<<B, THREADS>>>(scores, pos_mask, out);
}

// round 16
// speedup vs baseline: 1.3058x; 1.3058x over previous
#include <cuda_runtime.h>
#include <cuda_bf16.h>
#include <stdint.h>

#define B 128
#define C 1024
#define MARGIN 1.0f
#define THREADS 256
#define NWARP (THREADS / 32)
#define MAX_POS 256
#define VEC 4                 // C / THREADS

// Per-row (loss, denom) partials — distinct addresses, no contention.
__device__ float2 g_part[B];
// Last-block-done ticket; reset by the finishing block -> replay-safe.
__device__ unsigned int g_ticket;

// acq_rel RMW: release orders this block's prior partial store; for the block
// that observes ticket==B-1 it is also the acquire for reading all partials.
__device__ __forceinline__ unsigned int ticket_acq_rel_inc() {
    unsigned int t;
    asm volatile("atom.acq_rel.gpu.global.add.u32 %0, [%1], %2;"
                 : "=r"(t) : "l"(&g_ticket), "r"(1u) : "memory");
    return t;
}

__global__ void __launch_bounds__(THREADS, 1)
fused_kernel(const float* __restrict__ scores, const uint4* __restrict__ pos_mask,
             float* __restrict__ out) {
    const int row  = blockIdx.x;
    const int tid  = threadIdx.x;
    const int w    = tid >> 5;
    const int lane = tid & 31;

    __shared__ float s_pos[MAX_POS];
    __shared__ int   s_npos;
    __shared__ float s_red[NWARP];

    if (tid == 0) s_npos = 0;

    // Mask is a 32-bit dtype (float32 or int32 — established empirically).
    // For both: positive <=> 32-bit word != 0.
    // Scores + mask loads are independent: back-to-back, one latency round.
    const float4 sc4 = ((const float4*)(scores + row * C))[tid];
    const uint4  mv  = pos_mask[row * (C / VEC) + tid];

    __syncthreads();   // s_npos init visible; overlaps the in-flight loads

    float sc[VEC] = {sc4.x, sc4.y, sc4.z, sc4.w};
    bool  m[VEC]  = {mv.x != 0u, mv.y != 0u, mv.z != 0u, mv.w != 0u};

    // ---- Gather positive scores into SMEM (few positives -> cheap) ----
#pragma unroll
    for (int k = 0; k < VEC; k++) {
        if (m[k]) {
            int slot = atomicAdd(&s_npos, 1);
            if (slot < MAX_POS) s_pos[slot] = sc[k];
        }
    }
    __syncthreads();

    const int npos = min(s_npos, MAX_POS);

    // ---- Pairwise hinge with 4 independent accumulators (dep chain = npos) ----
    float a0 = 0.0f, a1 = 0.0f, a2 = 0.0f, a3 = 0.0f;
    {
        const float n0 = sc[0] + MARGIN, n1 = sc[1] + MARGIN;
        const float n2 = sc[2] + MARGIN, n3 = sc[3] + MARGIN;
        for (int p = 0; p < npos; p++) {
            const float sp = s_pos[p];
            if (!m[0]) a0 += fmaxf(n0 - sp, 0.0f);
            if (!m[1]) a1 += fmaxf(n1 - sp, 0.0f);
            if (!m[2]) a2 += fmaxf(n2 - sp, 0.0f);
            if (!m[3]) a3 += fmaxf(n3 - sp, 0.0f);
        }
    }
    float acc = (a0 + a1) + (a2 + a3);

    // ---- Deterministic block reduction ----
#pragma unroll
    for (int off = 16; off > 0; off >>= 1)
        acc += __shfl_down_sync(0xFFFFFFFFu, acc, off);
    if (lane == 0) s_red[w] = acc;
    __syncthreads();

    // ---- Warp 0 only: publish partial, grab ticket, maybe finalize.
    //      Warps 1..7 exit here (faster CTA drain). ----
    if (w == 0) {
        unsigned int ticket = 0;
        if (lane == 0) {
            // pairwise tree over 8 warp sums (fixed order -> deterministic)
            float t0 = s_red[0] + s_red[1];
            float t1 = s_red[2] + s_red[3];
            float t2 = s_red[4] + s_red[5];
            float t3 = s_red[6] + s_red[7];
            float total = (t0 + t1) + (t2 + t3);
            float np = (float)npos;
            __stcg(&g_part[row], make_float2(total, np * (float)(C - npos)));
            ticket = ticket_acq_rel_inc();  // release partial, fetch ticket
        }
        ticket = __shfl_sync(0xFFFFFFFFu, ticket, 0);

        if (ticket == B - 1) {
            // Last block: acquire done by the acq_rel atomic. Fixed-order,
            // bitwise-deterministic reduction of 128 partials in one warp.
            // 128 float2 = 64 float4: 2 vector loads per lane.
            const float4* p4 = (const float4*)g_part;
            float4 q0 = __ldcg(&p4[lane]);
            float4 q1 = __ldcg(&p4[lane + 32]);
            float l = q0.x + q0.z + q1.x + q1.z;
            float d = q0.y + q0.w + q1.y + q1.w;
#pragma unroll
            for (int off = 16; off > 0; off >>= 1) {
                l += __shfl_down_sync(0xFFFFFFFFu, l, off);
                d += __shfl_down_sync(0xFFFFFFFFu, d, off);
            }
            if (lane == 0) {
                out[0] = (d == 0.0f) ? 0.0f : l / d;
                g_ticket = 0;  // reset for next graph replay
            }
        }
    }
}

extern "C" void kernel_launch(void* const* d_in, const int* in_sizes, int n_in,
                              void* d_out, int out_size) {
    const float* scores = (const float*)d_in[0];
    const uint4* pos_mask = (const uint4*)d_in[1];
    float* out = (float*)d_out;

    fused_kernel<<<B, THREADS>>>(scores, pos_mask, out);
}